// round 11
// baseline (speedup 1.0000x reference)
#include <cuda_runtime.h>
#include <cuda_fp16.h>
#include <mma.h>
using namespace nvcuda;

// Fixed problem shape (SimpleGNN): N=100000 nodes, E=1600000 edges, dims 64->64->64
#define MAXN 100000
#define MAXE 1600000

// Scratch (device globals -- no runtime allocation allowed)
__device__ __half g_hbuf[MAXN * 64];   // fp16 pre-scaled message table
__device__ __half g_hact[MAXN * 64];   // fp16 hidden activations (layer-1 output)
__device__ int    g_indeg[MAXN];       // re-zeroed in k_scan3 (replay invariant)
__device__ int    g_incl[MAXN];
__device__ int    g_offs[MAXN + 1];    // exclusive offsets (immutable after scan3)
__device__ int    g_rank[MAXE];        // within-node rank of each edge (from hist)
__device__ int    g_csr[MAXE];         // src index only (weight folded into message)
__device__ float  g_dinv[MAXN];
__device__ int    g_bsums[128];        // per-1024-block totals from scan1

__device__ __forceinline__ unsigned h2_bits(__half2 h) {
    return *reinterpret_cast<unsigned*>(&h);
}
__device__ __forceinline__ float2 h2f2(unsigned bits) {
    return __half22float2(*reinterpret_cast<__half2*>(&bits));
}

// ---------------------------------------------------------------------------
// Histogram of in-degrees + per-edge rank (position within its node's segment)
// ---------------------------------------------------------------------------
__global__ void k_hist(const int* __restrict__ dst, int E) {
    int i = (blockIdx.x * blockDim.x + threadIdx.x) * 4;
    if (i + 4 <= E) {
        int4 d = __ldg((const int4*)(dst + i));
        int4 r;
        r.x = atomicAdd(&g_indeg[d.x], 1);
        r.y = atomicAdd(&g_indeg[d.y], 1);
        r.z = atomicAdd(&g_indeg[d.z], 1);
        r.w = atomicAdd(&g_indeg[d.w], 1);
        *(int4*)(g_rank + i) = r;
    } else {
        for (; i < E; i++) g_rank[i] = atomicAdd(&g_indeg[dst[i]], 1);
    }
}

// Block-wise inclusive scan of indeg (shfl); block totals -> g_bsums.
// Also emits dinv = rsqrt(indeg+1) so GEMM1 can fork right after this kernel.
__global__ __launch_bounds__(1024) void k_scan1(int n) {
    __shared__ int wsum[32];
    int t = threadIdx.x, lane = t & 31, w = t >> 5;
    int i = blockIdx.x * 1024 + t;
    int v = (i < n) ? g_indeg[i] : 0;
    int x = v;
    #pragma unroll
    for (int d = 1; d < 32; d <<= 1) {
        int y = __shfl_up_sync(0xffffffffu, x, d);
        if (lane >= d) x += y;
    }
    if (lane == 31) wsum[w] = x;
    __syncthreads();
    if (w == 0) {
        int y = wsum[lane];
        int z = y;
        #pragma unroll
        for (int d = 1; d < 32; d <<= 1) {
            int u = __shfl_up_sync(0xffffffffu, z, d);
            if (lane >= d) z += u;
        }
        wsum[lane] = z - y;  // exclusive warp offsets
    }
    __syncthreads();
    x += wsum[w];
    if (i < n) {
        g_incl[i] = x;
        g_dinv[i] = rsqrtf((float)(v + 1));
    }
    if (t == 1023) g_bsums[blockIdx.x] = x;
}

// Offsets: each 256-block lies in one 1024-chunk; warp 0 reduces bsums[0..chunk)
// (<=98 ints). Re-zeroes indeg for the next replay.
__global__ void k_scan3(int n) {
    __shared__ int s_pre;
    int chunk = (blockIdx.x * 256) >> 10;
    if (threadIdx.x < 32) {
        int acc = 0;
        for (int k = threadIdx.x; k < chunk; k += 32) acc += g_bsums[k];
        #pragma unroll
        for (int d = 16; d >= 1; d >>= 1) acc += __shfl_down_sync(0xffffffffu, acc, d);
        if (threadIdx.x == 0) s_pre = acc;
    }
    __syncthreads();
    int i = blockIdx.x * 256 + threadIdx.x;
    if (i < n) {
        int ind = g_indeg[i];
        int base = s_pre + g_incl[i];
        g_offs[i] = base - ind;
        if (i == n - 1) g_offs[n] = base;
        g_indeg[i] = 0;                      // ready for next replay
    }
}

// Atomic-free scatter: pos = offs[dst] + rank (rank precomputed in hist).
__global__ void k_fill(const int* __restrict__ src, const int* __restrict__ dst, int E) {
    int i = (blockIdx.x * blockDim.x + threadIdx.x) * 4;
    if (i + 4 <= E) {
        int4 s = __ldg((const int4*)(src + i));
        int4 d = __ldg((const int4*)(dst + i));
        int4 r = *(const int4*)(g_rank + i);
        g_csr[__ldg(&g_offs[d.x]) + r.x] = s.x;
        g_csr[__ldg(&g_offs[d.y]) + r.y] = s.y;
        g_csr[__ldg(&g_offs[d.z]) + r.z] = s.z;
        g_csr[__ldg(&g_offs[d.w]) + r.w] = s.w;
    } else {
        for (; i < E; i++) {
            g_csr[__ldg(&g_offs[dst[i]]) + g_rank[i]] = src[i];
        }
    }
}

// ---------------------------------------------------------------------------
// Tensor-core GEMM (HMMA via wmma) + fused dinv-scale + fp16 store:
//   m[r] = fp16(dinv[r] * (X@W)[r])
// 256 rows/block, 256 threads (8 warps). Warp w: rows [w*32, w*32+32).
// Acc frags: 2 m-tiles x 4 n-tiles of 16x16, fp32 accumulate.
// ---------------------------------------------------------------------------
#define XLD 72   // Xs leading dim (halves); 144B, multiple of 16B
#define SLD 20   // scratch leading dim (floats); 80B, multiple of 16B

template <typename T>
__global__ __launch_bounds__(256) void k_gemm64t(const T* __restrict__ X,
                                                 const float* __restrict__ W,
                                                 __half* __restrict__ Yh, int n) {
    __shared__ __half Ws[64 * 64];          // [k][n] row-major fp16, 8KB
    __shared__ __half Xs[256 * XLD];        // [row][k] fp16, 36KB
    __shared__ float  Sc[8][16 * SLD];      // per-warp epilogue scratch, 10.2KB

    int t = threadIdx.x;
    int w = t >> 5, lane = t & 31;
    int row0 = blockIdx.x * 256;

    // W: fp32 -> fp16 smem (row-major [k][n])
    for (int i = t; i < 4096; i += 256) Ws[i] = __float2half(W[i]);

    // X tile: 256 rows x 64 cols -> fp16 smem
    for (int i = t; i < 16384; i += 256) {
        int r = i >> 6, c = i & 63;
        int gr = row0 + r;
        float xv = (gr < n) ? (float)X[gr * 64 + c] : 0.f;
        Xs[r * XLD + c] = __float2half(xv);
    }
    __syncthreads();

    wmma::fragment<wmma::accumulator, 16, 16, 16, float> acc[2][4];
    #pragma unroll
    for (int mt = 0; mt < 2; mt++)
        #pragma unroll
        for (int nt = 0; nt < 4; nt++)
            wmma::fill_fragment(acc[mt][nt], 0.f);

    int mrow = w * 32;
    #pragma unroll
    for (int kc = 0; kc < 4; kc++) {
        wmma::fragment<wmma::matrix_a, 16, 16, 16, __half, wmma::row_major> af[2];
        wmma::load_matrix_sync(af[0], &Xs[mrow * XLD + kc * 16], XLD);
        wmma::load_matrix_sync(af[1], &Xs[(mrow + 16) * XLD + kc * 16], XLD);
        #pragma unroll
        for (int nt = 0; nt < 4; nt++) {
            wmma::fragment<wmma::matrix_b, 16, 16, 16, __half, wmma::row_major> bf;
            wmma::load_matrix_sync(bf, &Ws[(kc * 16) * 64 + nt * 16], 64);
            wmma::mma_sync(acc[0][nt], af[0], bf, acc[0][nt]);
            wmma::mma_sync(acc[1][nt], af[1], bf, acc[1][nt]);
        }
    }

    // Epilogue: per (mt,nt) tile -> warp scratch -> dinv scale -> fp16 global
    #pragma unroll
    for (int mt = 0; mt < 2; mt++) {
        #pragma unroll
        for (int nt = 0; nt < 4; nt++) {
            wmma::store_matrix_sync(&Sc[w][0], acc[mt][nt], SLD, wmma::mem_row_major);
            __syncwarp();
            int r = lane >> 1;               // 0..15
            int cb = (lane & 1) * 8;         // 0 or 8
            int gr = row0 + mrow + mt * 16 + r;
            if (gr < n) {
                float dv = __ldg(&g_dinv[gr]);
                const float* s = &Sc[w][r * SLD + cb];
                uint4 pk;
                pk.x = h2_bits(__floats2half2_rn(s[0] * dv, s[1] * dv));
                pk.y = h2_bits(__floats2half2_rn(s[2] * dv, s[3] * dv));
                pk.z = h2_bits(__floats2half2_rn(s[4] * dv, s[5] * dv));
                pk.w = h2_bits(__floats2half2_rn(s[6] * dv, s[7] * dv));
                *(uint4*)&Yh[gr * 64 + nt * 16 + cb] = pk;
            }
            __syncwarp();
        }
    }
}

// ---------------------------------------------------------------------------
// Pull aggregation with paired-edge gathers (R9 configuration).
// Warp = 1 node; 2 groups of 16 lanes; group g handles edges (e+2j+g);
// each lane gathers 8B of the 128B row -> one LDG.64 covers TWO edges per j.
// ---------------------------------------------------------------------------
template <bool HOUT>
__global__ __launch_bounds__(256) void k_agg(const uint2* __restrict__ xw,  // row = 16 uint2
                                             const float* __restrict__ bias,
                                             void* __restrict__ out, int n) {
    int v = (blockIdx.x * 256 + threadIdx.x) >> 5;
    int lane = threadIdx.x & 31;
    if (v >= n) return;
    int g = lane >> 4;       // edge-parity group (0: even edges, 1: odd edges)
    int c = lane & 15;       // 8-byte column slot within the 128B row

    float dv = g_dinv[v];
    float ax0 = 0.f, ay0 = 0.f, ax1 = 0.f, ay1 = 0.f;

    // self-loop message: group 0 only
    if (g == 0) {
        uint2 m = __ldg(&xw[v * 16 + c]);
        float2 a = h2f2(m.x), b = h2f2(m.y);
        ax0 = a.x; ay0 = a.y; ax1 = b.x; ay1 = b.y;
    }

    int e = __ldg(&g_offs[v]);
    int end = __ldg(&g_offs[v + 1]);

    // full batches: 16 edges (8 pairs) per iteration, 8 independent LDG.64
    for (; e + 16 <= end; e += 16) {
        #pragma unroll
        for (int j = 0; j < 8; j++) {
            int idx = __ldg(&g_csr[e + 2 * j + g]);
            uint2 m = __ldg(&xw[idx * 16 + c]);
            float2 a = h2f2(m.x), b = h2f2(m.y);
            ax0 += a.x; ay0 += a.y; ax1 += b.x; ay1 += b.y;
        }
    }
    // predicated tail: remaining <16 edges, still 8-deep in flight
    #pragma unroll
    for (int j = 0; j < 8; j++) {
        int ej = e + 2 * j + g;
        if (ej < end) {
            int idx = __ldg(&g_csr[ej]);
            uint2 m = __ldg(&xw[idx * 16 + c]);
            float2 a = h2f2(m.x), b = h2f2(m.y);
            ax0 += a.x; ay0 += a.y; ax1 += b.x; ay1 += b.y;
        }
    }

    // combine the two edge groups
    ax0 += __shfl_down_sync(0xffffffffu, ax0, 16);
    ay0 += __shfl_down_sync(0xffffffffu, ay0, 16);
    ax1 += __shfl_down_sync(0xffffffffu, ax1, 16);
    ay1 += __shfl_down_sync(0xffffffffu, ay1, 16);

    if (g == 0) {
        float4 bv = __ldg((const float4*)(bias + c * 4));
        float r0 = fmaxf(fmaf(ax0, dv, bv.x), 0.f);
        float r1 = fmaxf(fmaf(ay0, dv, bv.y), 0.f);
        float r2 = fmaxf(fmaf(ax1, dv, bv.z), 0.f);
        float r3 = fmaxf(fmaf(ay1, dv, bv.w), 0.f);
        if (HOUT) {
            uint2 o;
            o.x = h2_bits(__floats2half2_rn(r0, r1));
            o.y = h2_bits(__floats2half2_rn(r2, r3));
            ((uint2*)out)[v * 16 + c] = o;
        } else {
            ((float4*)out)[v * 16 + c] = make_float4(r0, r1, r2, r3);
        }
    }
}

// ---------------------------------------------------------------------------
extern "C" void kernel_launch(void* const* d_in, const int* in_sizes, int n_in,
                              void* d_out, int out_size) {
    const float* x  = (const float*)d_in[0];
    const int*   ei = (const int*)d_in[1];
    const float* W1 = (const float*)d_in[2];
    const float* b1 = (const float*)d_in[3];
    const float* W2 = (const float*)d_in[4];
    const float* b2 = (const float*)d_in[5];
    float* out = (float*)d_out;

    int N = in_sizes[0] / 64;
    int E = in_sizes[1] / 2;
    const int* src = ei;
    const int* dst = ei + E;
    int E4 = E / 4;

    int nbN = (N + 255) / 256;
    int nbE4 = (E4 + 255) / 256;
    int nbScan = (N + 1023) / 1024;
    int nbAgg = (N + 7) / 8;       // 8 warps per 256-thread block
    int nbGemm = (N + 255) / 256;  // 256 rows per tensor-core GEMM block

    __half* hbuf;  cudaGetSymbolAddress((void**)&hbuf, g_hbuf);
    __half* hact;  cudaGetSymbolAddress((void**)&hact, g_hact);

    // One-time side stream + events (created on the pre-capture correctness
    // call; reused by every call -> identical, deterministic launch pattern).
    static cudaStream_t s1 = nullptr;
    static cudaEvent_t evFork = nullptr, evJoin = nullptr;
    static bool streamsOk = false;
    static bool tried = false;
    if (!tried) {
        tried = true;
        streamsOk = (cudaStreamCreateWithFlags(&s1, cudaStreamNonBlocking) == cudaSuccess) &&
                    (cudaEventCreateWithFlags(&evFork, cudaEventDisableTiming) == cudaSuccess) &&
                    (cudaEventCreateWithFlags(&evJoin, cudaEventDisableTiming) == cudaSuccess);
    }

    // CSR build prologue. indeg starts zero (globals on call 1, re-zeroed by
    // scan3 on every call).
    k_hist<<<nbE4, 256>>>(dst, E);
    k_scan1<<<nbScan, 1024>>>(N);   // also produces dinv

    if (streamsOk) {
        // Fork: GEMM1 (needs dinv only) overlaps scan3+fill on main stream.
        cudaEventRecord(evFork, 0);
        cudaStreamWaitEvent(s1, evFork, 0);
        k_gemm64t<float><<<nbGemm, 256, 0, s1>>>(x, W1, hbuf, N);
        cudaEventRecord(evJoin, s1);

        k_scan3<<<nbN, 256>>>(N);
        k_fill<<<nbE4, 256>>>(src, dst, E);

        cudaStreamWaitEvent(0, evJoin, 0);
    } else {
        k_gemm64t<float><<<nbGemm, 256>>>(x, W1, hbuf, N);
        k_scan3<<<nbN, 256>>>(N);
        k_fill<<<nbE4, 256>>>(src, dst, E);
    }

    // Layer 1 aggregate (fp16 h), then layer 2
    k_agg<true><<<nbAgg, 256>>>((const uint2*)hbuf, b1, hact, N);
    k_gemm64t<__half><<<nbGemm, 256>>>(hact, W2, hbuf, N);
    k_agg<false><<<nbAgg, 256>>>((const uint2*)hbuf, b2, out, N);
}